// round 7
// baseline (speedup 1.0000x reference)
#include <cuda_runtime.h>
#include <math.h>
#include <stdint.h>

// Problem constants
#define B_   4
#define S_   2048
#define D_   1024
#define E_   1024
#define NH_  16
#define HD_  64
#define QKV_N (3 * E_)       // 3072
#define M_TOT (B_ * S_)      // 8192

// Scratch (device globals — allocation-free per harness rules)
__device__ float g_qkv[(size_t)M_TOT * QKV_N];   // [8192, 3072]
__device__ float g_vals[(size_t)M_TOT * E_];     // [8192, 1024]

// ----------------------------------------------------------------------------
// tf32 helpers
// ----------------------------------------------------------------------------
__device__ __forceinline__ float to_tf32(float x) {
    uint32_t u;
    asm("cvt.rna.tf32.f32 %0, %1;" : "=r"(u) : "f"(x));
    return __uint_as_float(u);
}

__device__ __forceinline__ void mma_tf32(float* c, const uint32_t* a,
                                         const uint32_t* b) {
    asm volatile(
        "mma.sync.aligned.m16n8k8.row.col.f32.tf32.tf32.f32 "
        "{%0,%1,%2,%3},{%4,%5,%6,%7},{%8,%9},{%0,%1,%2,%3};"
        : "+f"(c[0]), "+f"(c[1]), "+f"(c[2]), "+f"(c[3])
        : "r"(a[0]), "r"(a[1]), "r"(a[2]), "r"(a[3]),
          "r"(b[0]), "r"(b[1]));
}

// ----------------------------------------------------------------------------
// TF32 GEMM, warp tile 64x64: C[M,N] = A[M,K] @ B[N,K]^T (K-contiguous).
// CTA tile 128x256, BK=16, 256 threads (8 warps as 2 row-bands x 4 col-bands).
// 1.5x higher smem arithmetic intensity than the 64x32 variant.
// Dynamic smem: As[2][16][136] + Bs[2][16][264] = 51200 B.
// ----------------------------------------------------------------------------
#define ASTR 136
#define BSTR 264
#define GEMM_SMEM ((2 * 16 * ASTR + 2 * 16 * BSTR) * 4)   // 51200

__global__ __launch_bounds__(256) void sgemm_tf32w(
    const float* __restrict__ A, const float* __restrict__ Bm,
    float* __restrict__ C, int M, int N, int K)
{
    extern __shared__ float smx[];
    float* As = smx;                       // [2][16][ASTR]
    float* Bs = smx + 2 * 16 * ASTR;       // [2][16][BSTR]

    int tid  = threadIdx.x;
    int lane = tid & 31;
    int warp = tid >> 5;
    int wm  = warp & 1;      // 0..1 : 64-row band
    int wn  = warp >> 1;     // 0..3 : 64-col band
    int tig = lane & 3;
    int grp = lane >> 2;

    int m0 = blockIdx.y * 128;
    int n0 = blockIdx.x * 256;

    int lr  = tid >> 2;      // 0..63
    int lc4 = tid & 3;
    const float* Ald = A  + (size_t)(m0 + lr) * K + lc4 * 4;
    const float* Bld = Bm + (size_t)(n0 + lr) * K + lc4 * 4;
    size_t bandA = (size_t)64 * K;

    float acc[4][8][4];
#pragma unroll
    for (int i = 0; i < 4; i++)
#pragma unroll
        for (int j = 0; j < 8; j++)
#pragma unroll
            for (int r = 0; r < 4; r++) acc[i][j][r] = 0.f;

    float4 ar[2], br[4];
#pragma unroll
    for (int p = 0; p < 2; ++p) ar[p] = *(const float4*)(Ald + p * bandA);
#pragma unroll
    for (int p = 0; p < 4; ++p) br[p] = *(const float4*)(Bld + p * bandA);

    auto sts_tiles = [&](int buf) {
        float* Ab = As + buf * 16 * ASTR;
        float* Bb = Bs + buf * 16 * BSTR;
#pragma unroll
        for (int p = 0; p < 2; ++p) {
            int row = lr + p * 64;
            float4 v = ar[p];
            Ab[(lc4 * 4 + 0) * ASTR + row] = to_tf32(v.x);
            Ab[(lc4 * 4 + 1) * ASTR + row] = to_tf32(v.y);
            Ab[(lc4 * 4 + 2) * ASTR + row] = to_tf32(v.z);
            Ab[(lc4 * 4 + 3) * ASTR + row] = to_tf32(v.w);
        }
#pragma unroll
        for (int p = 0; p < 4; ++p) {
            int row = lr + p * 64;
            float4 v = br[p];
            Bb[(lc4 * 4 + 0) * BSTR + row] = to_tf32(v.x);
            Bb[(lc4 * 4 + 1) * BSTR + row] = to_tf32(v.y);
            Bb[(lc4 * 4 + 2) * BSTR + row] = to_tf32(v.z);
            Bb[(lc4 * 4 + 3) * BSTR + row] = to_tf32(v.w);
        }
    };

    sts_tiles(0);
    __syncthreads();

    int niter = K / 16;
    for (int kt = 0; kt < niter; ++kt) {
        int cur = kt & 1;

        if (kt + 1 < niter) {
            int off = (kt + 1) * 16;
#pragma unroll
            for (int p = 0; p < 2; ++p)
                ar[p] = *(const float4*)(Ald + p * bandA + off);
#pragma unroll
            for (int p = 0; p < 4; ++p)
                br[p] = *(const float4*)(Bld + p * bandA + off);
        }

        const float* Ab = As + cur * 16 * ASTR;
        const float* Bb = Bs + cur * 16 * BSTR;
#pragma unroll
        for (int ks = 0; ks < 16; ks += 8) {
            uint32_t af[4][4];
#pragma unroll
            for (int mt = 0; mt < 4; ++mt) {
                int mrow = wm * 64 + mt * 16 + grp;
                af[mt][0] = __float_as_uint(Ab[(ks + tig    ) * ASTR + mrow]);
                af[mt][1] = __float_as_uint(Ab[(ks + tig    ) * ASTR + mrow + 8]);
                af[mt][2] = __float_as_uint(Ab[(ks + tig + 4) * ASTR + mrow]);
                af[mt][3] = __float_as_uint(Ab[(ks + tig + 4) * ASTR + mrow + 8]);
            }
            uint32_t bf[8][2];
#pragma unroll
            for (int nt = 0; nt < 8; ++nt) {
                int ncol = wn * 64 + nt * 8 + grp;
                bf[nt][0] = __float_as_uint(Bb[(ks + tig    ) * BSTR + ncol]);
                bf[nt][1] = __float_as_uint(Bb[(ks + tig + 4) * BSTR + ncol]);
            }
#pragma unroll
            for (int mt = 0; mt < 4; ++mt)
#pragma unroll
                for (int nt = 0; nt < 8; ++nt)
                    mma_tf32(acc[mt][nt], af[mt], bf[nt]);
        }

        if (kt + 1 < niter) {
            sts_tiles(cur ^ 1);
            __syncthreads();
        }
    }

    // Epilogue: each warp writes its 64x64 region.
#pragma unroll
    for (int mt = 0; mt < 4; ++mt) {
#pragma unroll
        for (int nt = 0; nt < 8; ++nt) {
            int row = m0 + wm * 64 + mt * 16 + grp;
            int col = n0 + wn * 64 + nt * 8 + 2 * tig;
            *(float2*)(C + (size_t)row * N + col) =
                make_float2(acc[mt][nt][0], acc[mt][nt][1]);
            *(float2*)(C + (size_t)(row + 8) * N + col) =
                make_float2(acc[mt][nt][2], acc[mt][nt][3]);
        }
    }
}

// ----------------------------------------------------------------------------
// Tensor-core flash attention (tf32 legacy mma) — unchanged from round 5.
// ----------------------------------------------------------------------------
#define PSTR 68
#define VSTR 72

__global__ __launch_bounds__(256) void attn_tc(
    const float* __restrict__ qkv, float* __restrict__ vals)
{
    extern __shared__ float sm[];
    float* Pbuf = sm;                       // [128][PSTR]
    float* Ksm  = sm + 64 * PSTR;           // [64][PSTR] (rows 64..127 of Pbuf)
    float* Vsm  = sm + 128 * PSTR;          // [64][VSTR]

    int tid  = threadIdx.x;
    int lane = tid & 31;
    int warp = tid >> 5;
    int grp  = lane >> 2;
    int tig  = lane & 3;

    int qb = blockIdx.x;
    int h  = blockIdx.y;
    int b  = blockIdx.z;

    const float* base = qkv + (size_t)b * S_ * QKV_N + h * (3 * HD_);
    const float* qg = base;
    const float* kg = base + HD_;
    const float* vg = base + 2 * HD_;
    int q0 = qb * 128;

#pragma unroll
    for (int p = 0; p < 8; ++p) {
        int idx = tid + p * 256;
        int row = idx >> 4;
        int c4  = idx & 15;
        float4 v = *(const float4*)(qg + (size_t)(q0 + row) * QKV_N + c4 * 4);
        float4 t;
        t.x = to_tf32(v.x * 0.125f);
        t.y = to_tf32(v.y * 0.125f);
        t.z = to_tf32(v.z * 0.125f);
        t.w = to_tf32(v.w * 0.125f);
        *(float4*)(Pbuf + row * PSTR + c4 * 4) = t;
    }
    __syncthreads();

    uint32_t qf[8][4];
    {
        int r0 = warp * 16 + grp;
#pragma unroll
        for (int ks = 0; ks < 8; ++ks) {
            qf[ks][0] = __float_as_uint(Pbuf[r0 * PSTR + 8 * ks + tig]);
            qf[ks][1] = __float_as_uint(Pbuf[(r0 + 8) * PSTR + 8 * ks + tig]);
            qf[ks][2] = __float_as_uint(Pbuf[r0 * PSTR + 8 * ks + tig + 4]);
            qf[ks][3] = __float_as_uint(Pbuf[(r0 + 8) * PSTR + 8 * ks + tig + 4]);
        }
    }

    float m_i[2] = {-1e30f, -1e30f};
    float l_i[2] = {0.f, 0.f};
    float oacc[8][4];
#pragma unroll
    for (int nt = 0; nt < 8; ++nt)
#pragma unroll
        for (int r = 0; r < 4; ++r) oacc[nt][r] = 0.f;

    for (int kt = 0; kt < S_; kt += 64) {
        __syncthreads();

#pragma unroll
        for (int p = 0; p < 4; ++p) {
            int idx = tid + p * 256;
            int row = idx >> 4;
            int c4  = idx & 15;
            float4 v = *(const float4*)(kg + (size_t)(kt + row) * QKV_N + c4 * 4);
            float4 t;
            t.x = to_tf32(v.x); t.y = to_tf32(v.y);
            t.z = to_tf32(v.z); t.w = to_tf32(v.w);
            *(float4*)(Ksm + row * PSTR + c4 * 4) = t;
            float4 w = *(const float4*)(vg + (size_t)(kt + row) * QKV_N + c4 * 4);
            float4 u;
            u.x = to_tf32(w.x); u.y = to_tf32(w.y);
            u.z = to_tf32(w.z); u.w = to_tf32(w.w);
            *(float4*)(Vsm + row * VSTR + c4 * 4) = u;
        }
        __syncthreads();

        float sacc[8][4];
#pragma unroll
        for (int nt = 0; nt < 8; ++nt)
#pragma unroll
            for (int r = 0; r < 4; ++r) sacc[nt][r] = 0.f;

#pragma unroll
        for (int ks = 0; ks < 8; ++ks) {
            uint32_t bf[8][2];
#pragma unroll
            for (int nt = 0; nt < 8; ++nt) {
                bf[nt][0] = __float_as_uint(Ksm[(nt * 8 + grp) * PSTR + 8 * ks + tig]);
                bf[nt][1] = __float_as_uint(Ksm[(nt * 8 + grp) * PSTR + 8 * ks + tig + 4]);
            }
#pragma unroll
            for (int nt = 0; nt < 8; ++nt)
                mma_tf32(sacc[nt], qf[ks], bf[nt]);
        }
        __syncthreads();

        float mx0 = -1e30f, mx1 = -1e30f;
#pragma unroll
        for (int nt = 0; nt < 8; ++nt) {
            mx0 = fmaxf(mx0, fmaxf(sacc[nt][0], sacc[nt][1]));
            mx1 = fmaxf(mx1, fmaxf(sacc[nt][2], sacc[nt][3]));
        }
        mx0 = fmaxf(mx0, __shfl_xor_sync(0xffffffffu, mx0, 1));
        mx0 = fmaxf(mx0, __shfl_xor_sync(0xffffffffu, mx0, 2));
        mx1 = fmaxf(mx1, __shfl_xor_sync(0xffffffffu, mx1, 1));
        mx1 = fmaxf(mx1, __shfl_xor_sync(0xffffffffu, mx1, 2));

        float mn0 = fmaxf(m_i[0], mx0);
        float mn1 = fmaxf(m_i[1], mx1);
        float f0 = __expf(m_i[0] - mn0);
        float f1 = __expf(m_i[1] - mn1);
        m_i[0] = mn0; m_i[1] = mn1;

        int r0 = warp * 16 + grp;
        float rs0 = 0.f, rs1 = 0.f;
#pragma unroll
        for (int nt = 0; nt < 8; ++nt) {
            float p0 = __expf(sacc[nt][0] - mn0);
            float p1 = __expf(sacc[nt][1] - mn0);
            float p2 = __expf(sacc[nt][2] - mn1);
            float p3 = __expf(sacc[nt][3] - mn1);
            rs0 += p0 + p1;
            rs1 += p2 + p3;
            *(float2*)(Pbuf + r0 * PSTR + nt * 8 + 2 * tig) =
                make_float2(to_tf32(p0), to_tf32(p1));
            *(float2*)(Pbuf + (r0 + 8) * PSTR + nt * 8 + 2 * tig) =
                make_float2(to_tf32(p2), to_tf32(p3));
        }
        rs0 += __shfl_xor_sync(0xffffffffu, rs0, 1);
        rs0 += __shfl_xor_sync(0xffffffffu, rs0, 2);
        rs1 += __shfl_xor_sync(0xffffffffu, rs1, 1);
        rs1 += __shfl_xor_sync(0xffffffffu, rs1, 2);
        l_i[0] = l_i[0] * f0 + rs0;
        l_i[1] = l_i[1] * f1 + rs1;

#pragma unroll
        for (int nt = 0; nt < 8; ++nt) {
            oacc[nt][0] *= f0; oacc[nt][1] *= f0;
            oacc[nt][2] *= f1; oacc[nt][3] *= f1;
        }
        __syncthreads();

#pragma unroll
        for (int ks = 0; ks < 8; ++ks) {
            uint32_t af[4];
            af[0] = __float_as_uint(Pbuf[r0 * PSTR + 8 * ks + tig]);
            af[1] = __float_as_uint(Pbuf[(r0 + 8) * PSTR + 8 * ks + tig]);
            af[2] = __float_as_uint(Pbuf[r0 * PSTR + 8 * ks + tig + 4]);
            af[3] = __float_as_uint(Pbuf[(r0 + 8) * PSTR + 8 * ks + tig + 4]);
#pragma unroll
            for (int nt = 0; nt < 8; ++nt) {
                uint32_t bf[2];
                bf[0] = __float_as_uint(Vsm[(8 * ks + tig) * VSTR + nt * 8 + grp]);
                bf[1] = __float_as_uint(Vsm[(8 * ks + tig + 4) * VSTR + nt * 8 + grp]);
                mma_tf32(oacc[nt], af, bf);
            }
        }
    }

    float inv0 = 1.f / l_i[0];
    float inv1 = 1.f / l_i[1];
    size_t row0 = (size_t)b * S_ + q0 + warp * 16 + grp;
#pragma unroll
    for (int nt = 0; nt < 8; ++nt) {
        int col = h * HD_ + nt * 8 + 2 * tig;
        *(float2*)(vals + row0 * E_ + col) =
            make_float2(oacc[nt][0] * inv0, oacc[nt][1] * inv0);
        *(float2*)(vals + (row0 + 8) * E_ + col) =
            make_float2(oacc[nt][2] * inv1, oacc[nt][3] * inv1);
    }
}

// ----------------------------------------------------------------------------
// Launch
// ----------------------------------------------------------------------------
#define ATTN_SMEM ((128 * PSTR + 64 * VSTR) * 4)   // 53248 bytes

extern "C" void kernel_launch(void* const* d_in, const int* in_sizes, int n_in,
                              void* d_out, int out_size)
{
    (void)in_sizes; (void)n_in; (void)out_size;
    const float* x     = (const float*)d_in[0];
    const float* qkv_w = (const float*)d_in[1];
    const float* o_w   = (const float*)d_in[2];
    float* out = (float*)d_out;

    static float* qkv_buf = nullptr;
    static float* vals_buf = nullptr;
    if (qkv_buf == nullptr) {
        cudaGetSymbolAddress((void**)&qkv_buf, g_qkv);
        cudaGetSymbolAddress((void**)&vals_buf, g_vals);
        cudaFuncSetAttribute(attn_tc,
                             cudaFuncAttributeMaxDynamicSharedMemorySize,
                             ATTN_SMEM);
        cudaFuncSetAttribute(sgemm_tf32w,
                             cudaFuncAttributeMaxDynamicSharedMemorySize,
                             GEMM_SMEM);
    }

    dim3 blk(256);
    // 1) qkv = x @ qkv_w^T : [8192,1024] x [3072,1024]^T -> [8192,3072]
    sgemm_tf32w<<<dim3(QKV_N / 256, M_TOT / 128), blk, GEMM_SMEM>>>(
        x, qkv_w, qkv_buf, M_TOT, QKV_N, D_);
    // 2) attention -> vals
    attn_tc<<<dim3(S_ / 128, NH_, B_), blk, ATTN_SMEM>>>(qkv_buf, vals_buf);
    // 3) out = vals @ o_w^T : [8192,1024] x [1024,1024]^T -> [8192,1024]
    sgemm_tf32w<<<dim3(E_ / 256, M_TOT / 128), blk, GEMM_SMEM>>>(
        vals_buf, o_w, out, M_TOT, E_, D_);
}

// round 10
// speedup vs baseline: 1.1246x; 1.1246x over previous
#include <cuda_runtime.h>
#include <math.h>
#include <stdint.h>

// Problem constants
#define B_   4
#define S_   2048
#define D_   1024
#define E_   1024
#define NH_  16
#define HD_  64
#define QKV_N (3 * E_)       // 3072
#define M_TOT (B_ * S_)      // 8192

// Scratch (device globals — allocation-free per harness rules)
__device__ float g_qkv[(size_t)M_TOT * QKV_N];   // [8192, 3072]
__device__ float g_vals[(size_t)M_TOT * E_];     // [8192, 1024]

// ----------------------------------------------------------------------------
// tf32 helpers
// ----------------------------------------------------------------------------
__device__ __forceinline__ float to_tf32(float x) {
    uint32_t u;
    asm("cvt.rna.tf32.f32 %0, %1;" : "=r"(u) : "f"(x));
    return __uint_as_float(u);
}

__device__ __forceinline__ void mma_tf32(float* c, const uint32_t* a,
                                         const uint32_t* b) {
    asm volatile(
        "mma.sync.aligned.m16n8k8.row.col.f32.tf32.tf32.f32 "
        "{%0,%1,%2,%3},{%4,%5,%6,%7},{%8,%9},{%0,%1,%2,%3};"
        : "+f"(c[0]), "+f"(c[1]), "+f"(c[2]), "+f"(c[3])
        : "r"(a[0]), "r"(a[1]), "r"(a[2]), "r"(a[3]),
          "r"(b[0]), "r"(b[1]));
}

// ----------------------------------------------------------------------------
// TF32 tensor-core GEMM (round-2 proven version): C = A[M,K] @ B[N,K]^T
// 128x128 block tile, BK=16, 256 threads (8 warps as 2x4), warp tile 64x32.
// 128 regs -> 2 CTAs/SM.
// ----------------------------------------------------------------------------
__global__ __launch_bounds__(256) void sgemm_tf32(
    const float* __restrict__ A, const float* __restrict__ Bm,
    float* __restrict__ C, int M, int N, int K)
{
    __shared__ float As[2][16][136];
    __shared__ float Bs[2][16][136];

    int tid  = threadIdx.x;
    int lane = tid & 31;
    int warp = tid >> 5;
    int wm = warp & 1;
    int wn = warp >> 1;
    int tig = lane & 3;
    int grp = lane >> 2;

    int m0 = blockIdx.y * 128;
    int n0 = blockIdx.x * 128;

    int lr  = tid >> 2;
    int lc4 = tid & 3;
    const float* Ald = A  + (size_t)(m0 + lr) * K + lc4 * 4;
    const float* Bld = Bm + (size_t)(n0 + lr) * K + lc4 * 4;
    size_t half = (size_t)64 * K;

    float acc[4][4][4];
#pragma unroll
    for (int i = 0; i < 4; i++)
#pragma unroll
        for (int j = 0; j < 4; j++)
#pragma unroll
            for (int r = 0; r < 4; r++) acc[i][j][r] = 0.f;

    float4 ar[2], br[2];
    ar[0] = *(const float4*)(Ald);
    ar[1] = *(const float4*)(Ald + half);
    br[0] = *(const float4*)(Bld);
    br[1] = *(const float4*)(Bld + half);

    auto sts_tiles = [&](int buf) {
#pragma unroll
        for (int p = 0; p < 2; ++p) {
            int row = lr + p * 64;
            float4 va = ar[p];
            As[buf][lc4 * 4 + 0][row] = to_tf32(va.x);
            As[buf][lc4 * 4 + 1][row] = to_tf32(va.y);
            As[buf][lc4 * 4 + 2][row] = to_tf32(va.z);
            As[buf][lc4 * 4 + 3][row] = to_tf32(va.w);
            float4 vb = br[p];
            Bs[buf][lc4 * 4 + 0][row] = to_tf32(vb.x);
            Bs[buf][lc4 * 4 + 1][row] = to_tf32(vb.y);
            Bs[buf][lc4 * 4 + 2][row] = to_tf32(vb.z);
            Bs[buf][lc4 * 4 + 3][row] = to_tf32(vb.w);
        }
    };

    sts_tiles(0);
    __syncthreads();

    int niter = K / 16;
    for (int kt = 0; kt < niter; ++kt) {
        int cur = kt & 1;

        if (kt + 1 < niter) {
            int off = (kt + 1) * 16;
            ar[0] = *(const float4*)(Ald + off);
            ar[1] = *(const float4*)(Ald + half + off);
            br[0] = *(const float4*)(Bld + off);
            br[1] = *(const float4*)(Bld + half + off);
        }

#pragma unroll
        for (int ks = 0; ks < 16; ks += 8) {
            uint32_t af[4][4];
#pragma unroll
            for (int mt = 0; mt < 4; ++mt) {
                int mrow = wm * 64 + mt * 16 + grp;
                af[mt][0] = __float_as_uint(As[cur][ks + tig    ][mrow]);
                af[mt][1] = __float_as_uint(As[cur][ks + tig    ][mrow + 8]);
                af[mt][2] = __float_as_uint(As[cur][ks + tig + 4][mrow]);
                af[mt][3] = __float_as_uint(As[cur][ks + tig + 4][mrow + 8]);
            }
            uint32_t bf[4][2];
#pragma unroll
            for (int nt = 0; nt < 4; ++nt) {
                int ncol = wn * 32 + nt * 8 + grp;
                bf[nt][0] = __float_as_uint(Bs[cur][ks + tig    ][ncol]);
                bf[nt][1] = __float_as_uint(Bs[cur][ks + tig + 4][ncol]);
            }
#pragma unroll
            for (int mt = 0; mt < 4; ++mt)
#pragma unroll
                for (int nt = 0; nt < 4; ++nt)
                    mma_tf32(acc[mt][nt], af[mt], bf[nt]);
        }

        if (kt + 1 < niter) {
            sts_tiles(cur ^ 1);
            __syncthreads();
        }
    }

#pragma unroll
    for (int mt = 0; mt < 4; ++mt) {
#pragma unroll
        for (int nt = 0; nt < 4; ++nt) {
            int row = m0 + wm * 64 + mt * 16 + grp;
            int col = n0 + wn * 32 + nt * 8 + 2 * tig;
            *(float2*)(C + (size_t)row * N + col) =
                make_float2(acc[mt][nt][0], acc[mt][nt][1]);
            *(float2*)(C + (size_t)(row + 8) * N + col) =
                make_float2(acc[mt][nt][2], acc[mt][nt][3]);
        }
    }
}

// ----------------------------------------------------------------------------
// Tensor-core flash attention (tf32 mma), occupancy-2 version.
// One CTA = (b, h, 128-query block). 8 warps x 16 query rows, BN=64.
// Q staged in its own smem buffer; fragments reloaded per ks-step so the
// register count fits 128 (-> 2 CTAs/SM, stalls overlap across CTAs).
// Smem 86KB: Pbuf[128][68] (upper half aliases K tile) + Vs[64][72] + Qs[128][68].
// ----------------------------------------------------------------------------
#define PSTR 68
#define VSTR 72

__global__ __launch_bounds__(256, 2) void attn_tc(
    const float* __restrict__ qkv, float* __restrict__ vals)
{
    extern __shared__ float sm[];
    float* Pbuf = sm;                              // [128][PSTR]
    float* Ksm  = sm + 64 * PSTR;                  // rows 64..127 of Pbuf
    float* Vsm  = sm + 128 * PSTR;                 // [64][VSTR]
    float* Qsm  = sm + 128 * PSTR + 64 * VSTR;     // [128][PSTR]

    int tid  = threadIdx.x;
    int lane = tid & 31;
    int warp = tid >> 5;
    int grp  = lane >> 2;
    int tig  = lane & 3;

    int qb = blockIdx.x;
    int h  = blockIdx.y;
    int b  = blockIdx.z;

    const float* base = qkv + (size_t)b * S_ * QKV_N + h * (3 * HD_);
    const float* qg = base;
    const float* kg = base + HD_;
    const float* vg = base + 2 * HD_;
    int q0 = qb * 128;
    int r0 = warp * 16 + grp;

    // ---- Stage Q (scaled, tf32) into Qsm ----
#pragma unroll
    for (int p = 0; p < 8; ++p) {
        int idx = tid + p * 256;            // 0..2047
        int row = idx >> 4;
        int c4  = idx & 15;
        float4 v = *(const float4*)(qg + (size_t)(q0 + row) * QKV_N + c4 * 4);
        float4 t;
        t.x = to_tf32(v.x * 0.125f);
        t.y = to_tf32(v.y * 0.125f);
        t.z = to_tf32(v.z * 0.125f);
        t.w = to_tf32(v.w * 0.125f);
        *(float4*)(Qsm + row * PSTR + c4 * 4) = t;
    }

    float m_i[2] = {-1e30f, -1e30f};
    float l_i[2] = {0.f, 0.f};
    float oacc[8][4];
#pragma unroll
    for (int nt = 0; nt < 8; ++nt)
#pragma unroll
        for (int r = 0; r < 4; ++r) oacc[nt][r] = 0.f;

    __syncthreads();   // Qsm visible

    for (int kt = 0; kt < S_; kt += 64) {
        // ---- Load K tile (tf32) into Ksm, V tile (tf32) into Vsm ----
#pragma unroll
        for (int p = 0; p < 4; ++p) {
            int idx = tid + p * 256;        // 0..1023
            int row = idx >> 4;
            int c4  = idx & 15;
            float4 v = *(const float4*)(kg + (size_t)(kt + row) * QKV_N + c4 * 4);
            float4 t;
            t.x = to_tf32(v.x); t.y = to_tf32(v.y);
            t.z = to_tf32(v.z); t.w = to_tf32(v.w);
            *(float4*)(Ksm + row * PSTR + c4 * 4) = t;
            float4 w = *(const float4*)(vg + (size_t)(kt + row) * QKV_N + c4 * 4);
            float4 u;
            u.x = to_tf32(w.x); u.y = to_tf32(w.y);
            u.z = to_tf32(w.z); u.w = to_tf32(w.w);
            *(float4*)(Vsm + row * VSTR + c4 * 4) = u;
        }
        __syncthreads();

        // ---- S = Q @ K^T  (warp: 16 rows x 64 keys) ----
        float sacc[8][4];
#pragma unroll
        for (int nt = 0; nt < 8; ++nt)
#pragma unroll
            for (int r = 0; r < 4; ++r) sacc[nt][r] = 0.f;

#pragma unroll
        for (int ks = 0; ks < 8; ++ks) {
            uint32_t qf[4];
            qf[0] = __float_as_uint(Qsm[r0 * PSTR + 8 * ks + tig]);
            qf[1] = __float_as_uint(Qsm[(r0 + 8) * PSTR + 8 * ks + tig]);
            qf[2] = __float_as_uint(Qsm[r0 * PSTR + 8 * ks + tig + 4]);
            qf[3] = __float_as_uint(Qsm[(r0 + 8) * PSTR + 8 * ks + tig + 4]);
            uint32_t bf[8][2];
#pragma unroll
            for (int nt = 0; nt < 8; ++nt) {
                bf[nt][0] = __float_as_uint(Ksm[(nt * 8 + grp) * PSTR + 8 * ks + tig]);
                bf[nt][1] = __float_as_uint(Ksm[(nt * 8 + grp) * PSTR + 8 * ks + tig + 4]);
            }
#pragma unroll
            for (int nt = 0; nt < 8; ++nt)
                mma_tf32(sacc[nt], qf, bf[nt]);
        }
        __syncthreads();   // all warps done reading Ksm (aliased w/ Pbuf)

        // ---- Online softmax (rows r0, r0+8) ----
        float mx0 = -1e30f, mx1 = -1e30f;
#pragma unroll
        for (int nt = 0; nt < 8; ++nt) {
            mx0 = fmaxf(mx0, fmaxf(sacc[nt][0], sacc[nt][1]));
            mx1 = fmaxf(mx1, fmaxf(sacc[nt][2], sacc[nt][3]));
        }
        mx0 = fmaxf(mx0, __shfl_xor_sync(0xffffffffu, mx0, 1));
        mx0 = fmaxf(mx0, __shfl_xor_sync(0xffffffffu, mx0, 2));
        mx1 = fmaxf(mx1, __shfl_xor_sync(0xffffffffu, mx1, 1));
        mx1 = fmaxf(mx1, __shfl_xor_sync(0xffffffffu, mx1, 2));

        float mn0 = fmaxf(m_i[0], mx0);
        float mn1 = fmaxf(m_i[1], mx1);
        float f0 = __expf(m_i[0] - mn0);
        float f1 = __expf(m_i[1] - mn1);
        m_i[0] = mn0; m_i[1] = mn1;

        float rs0 = 0.f, rs1 = 0.f;
#pragma unroll
        for (int nt = 0; nt < 8; ++nt) {
            float p0 = __expf(sacc[nt][0] - mn0);
            float p1 = __expf(sacc[nt][1] - mn0);
            float p2 = __expf(sacc[nt][2] - mn1);
            float p3 = __expf(sacc[nt][3] - mn1);
            rs0 += p0 + p1;
            rs1 += p2 + p3;
            *(float2*)(Pbuf + r0 * PSTR + nt * 8 + 2 * tig) =
                make_float2(to_tf32(p0), to_tf32(p1));
            *(float2*)(Pbuf + (r0 + 8) * PSTR + nt * 8 + 2 * tig) =
                make_float2(to_tf32(p2), to_tf32(p3));
        }
        rs0 += __shfl_xor_sync(0xffffffffu, rs0, 1);
        rs0 += __shfl_xor_sync(0xffffffffu, rs0, 2);
        rs1 += __shfl_xor_sync(0xffffffffu, rs1, 1);
        rs1 += __shfl_xor_sync(0xffffffffu, rs1, 2);
        l_i[0] = l_i[0] * f0 + rs0;
        l_i[1] = l_i[1] * f1 + rs1;

#pragma unroll
        for (int nt = 0; nt < 8; ++nt) {
            oacc[nt][0] *= f0; oacc[nt][1] *= f0;
            oacc[nt][2] *= f1; oacc[nt][3] *= f1;
        }
        __syncthreads();   // P visible to all warps

        // ---- O += P @ V ----
#pragma unroll
        for (int ks = 0; ks < 8; ++ks) {
            uint32_t af[4];
            af[0] = __float_as_uint(Pbuf[r0 * PSTR + 8 * ks + tig]);
            af[1] = __float_as_uint(Pbuf[(r0 + 8) * PSTR + 8 * ks + tig]);
            af[2] = __float_as_uint(Pbuf[r0 * PSTR + 8 * ks + tig + 4]);
            af[3] = __float_as_uint(Pbuf[(r0 + 8) * PSTR + 8 * ks + tig + 4]);
#pragma unroll
            for (int nt = 0; nt < 8; ++nt) {
                uint32_t bf[2];
                bf[0] = __float_as_uint(Vsm[(8 * ks + tig) * VSTR + nt * 8 + grp]);
                bf[1] = __float_as_uint(Vsm[(8 * ks + tig + 4) * VSTR + nt * 8 + grp]);
                mma_tf32(oacc[nt], af, bf);
            }
        }
        __syncthreads();   // PV reads of Pbuf/Vsm done before next K/V load
    }

    // ---- Epilogue: normalize, write vals[b, q, h*64 + d] ----
    float inv0 = 1.f / l_i[0];
    float inv1 = 1.f / l_i[1];
    size_t row0 = (size_t)b * S_ + q0 + r0;
#pragma unroll
    for (int nt = 0; nt < 8; ++nt) {
        int col = h * HD_ + nt * 8 + 2 * tig;
        *(float2*)(vals + row0 * E_ + col) =
            make_float2(oacc[nt][0] * inv0, oacc[nt][1] * inv0);
        *(float2*)(vals + (row0 + 8) * E_ + col) =
            make_float2(oacc[nt][2] * inv1, oacc[nt][3] * inv1);
    }
}

// ----------------------------------------------------------------------------
// Launch
// ----------------------------------------------------------------------------
#define ATTN_SMEM ((128 * PSTR + 64 * VSTR + 128 * PSTR) * 4)   // 88064 bytes

extern "C" void kernel_launch(void* const* d_in, const int* in_sizes, int n_in,
                              void* d_out, int out_size)
{
    (void)in_sizes; (void)n_in; (void)out_size;
    const float* x     = (const float*)d_in[0];
    const float* qkv_w = (const float*)d_in[1];
    const float* o_w   = (const float*)d_in[2];
    float* out = (float*)d_out;

    static float* qkv_buf = nullptr;
    static float* vals_buf = nullptr;
    if (qkv_buf == nullptr) {
        cudaGetSymbolAddress((void**)&qkv_buf, g_qkv);
        cudaGetSymbolAddress((void**)&vals_buf, g_vals);
        cudaFuncSetAttribute(attn_tc,
                             cudaFuncAttributeMaxDynamicSharedMemorySize,
                             ATTN_SMEM);
    }

    dim3 blk(256);
    // 1) qkv = x @ qkv_w^T
    sgemm_tf32<<<dim3(QKV_N / 128, M_TOT / 128), blk>>>(x, qkv_w, qkv_buf,
                                                        M_TOT, QKV_N, D_);
    // 2) attention -> vals
    attn_tc<<<dim3(S_ / 128, NH_, B_), blk, ATTN_SMEM>>>(qkv_buf, vals_buf);
    // 3) out = vals @ o_w^T
    sgemm_tf32<<<dim3(E_ / 128, M_TOT / 128), blk>>>(vals_buf, o_w, out,
                                                     M_TOT, E_, D_);
}

// round 11
// speedup vs baseline: 1.1739x; 1.0438x over previous
#include <cuda_runtime.h>
#include <math.h>
#include <stdint.h>

// Problem constants
#define B_   4
#define S_   2048
#define D_   1024
#define E_   1024
#define NH_  16
#define HD_  64
#define QKV_N (3 * E_)       // 3072
#define M_TOT (B_ * S_)      // 8192

// Scratch (device globals — allocation-free per harness rules)
__device__ float g_qkv[(size_t)M_TOT * QKV_N];   // [8192, 3072]
__device__ float g_vals[(size_t)M_TOT * E_];     // [8192, 1024] (tf32-valued)
__device__ float g_xc[(size_t)M_TOT * D_];       // x, tf32-rounded
__device__ float g_wc[(size_t)QKV_N * D_];       // qkv_w, tf32-rounded
__device__ float g_oc[(size_t)E_ * D_];          // o_w, tf32-rounded

// ----------------------------------------------------------------------------
// tf32 helpers
// ----------------------------------------------------------------------------
__device__ __forceinline__ float to_tf32(float x) {
    uint32_t u;
    asm("cvt.rna.tf32.f32 %0, %1;" : "=r"(u) : "f"(x));
    return __uint_as_float(u);
}

__device__ __forceinline__ void mma_tf32(float* c, const uint32_t* a,
                                         const uint32_t* b) {
    asm volatile(
        "mma.sync.aligned.m16n8k8.row.col.f32.tf32.tf32.f32 "
        "{%0,%1,%2,%3},{%4,%5,%6,%7},{%8,%9},{%0,%1,%2,%3};"
        : "+f"(c[0]), "+f"(c[1]), "+f"(c[2]), "+f"(c[3])
        : "r"(a[0]), "r"(a[1]), "r"(a[2]), "r"(a[3]),
          "r"(b[0]), "r"(b[1]));
}

__device__ __forceinline__ void cp16(uint32_t saddr, const void* g) {
    asm volatile("cp.async.cg.shared.global [%0], [%1], 16;"
                 :: "r"(saddr), "l"(g) : "memory");
}
__device__ __forceinline__ void cp_commit() {
    asm volatile("cp.async.commit_group;" ::: "memory");
}
template <int N>
__device__ __forceinline__ void cp_wait() {
    asm volatile("cp.async.wait_group %0;" :: "n"(N) : "memory");
}

// ----------------------------------------------------------------------------
// Pre-round a tensor to tf32-valued fp32 (RNA), 4 elems/thread.
// ----------------------------------------------------------------------------
__global__ __launch_bounds__(256) void cvt_tf32_kernel(
    const float* __restrict__ in, float* __restrict__ out, int n4)
{
    int i = blockIdx.x * blockDim.x + threadIdx.x;
    if (i < n4) {
        float4 v = ((const float4*)in)[i];
        float4 t;
        t.x = to_tf32(v.x); t.y = to_tf32(v.y);
        t.z = to_tf32(v.z); t.w = to_tf32(v.w);
        ((float4*)out)[i] = t;
    }
}

// ----------------------------------------------------------------------------
// cp.async tf32 GEMM: C[M,N] = A[M,K] @ B[N,K]^T. Operands MUST already be
// tf32-valued fp32 (lower mantissa bits zero). 128x128 tile, BK=16, 4-stage
// cp.async.cg pipeline, natural [row][k] smem layout, stride 20 floats
// (conflict-free fragment LDS: (8k*20+tig) mod 32 covers 32 banks).
// Dynamic smem: 4 stages x (A 10240B + B 10240B) = 81920B. 2 CTAs/SM.
// ----------------------------------------------------------------------------
#define GSTR 20
#define STAGE_B (2 * 128 * GSTR * 4)            // 20480 bytes
#define GEMM_SMEM (4 * STAGE_B)                  // 81920 bytes

__global__ __launch_bounds__(256, 2) void gemm_ca(
    const float* __restrict__ A, const float* __restrict__ Bm,
    float* __restrict__ C, int M, int N, int K)
{
    extern __shared__ float smf[];
    uint32_t sb = (uint32_t)__cvta_generic_to_shared(smf);

    int tid  = threadIdx.x;
    int lane = tid & 31;
    int warp = tid >> 5;
    int wm = warp & 1;
    int wn = warp >> 1;
    int tig = lane & 3;
    int grp = lane >> 2;

    int m0 = blockIdx.y * 128;
    int n0 = blockIdx.x * 128;

    // Loader mapping: each thread does 2 A-chunks + 2 B-chunks of 16B.
    int lrow = tid >> 1;           // 0..127
    int cb   = (tid & 1) * 2;      // chunk base 0 or 2 (of 4 per row)
    const float* Ag = A  + (size_t)(m0 + lrow) * K + cb * 4;
    const float* Bg = Bm + (size_t)(n0 + lrow) * K + cb * 4;
    uint32_t As_s = sb + lrow * (GSTR * 4) + cb * 16;
    uint32_t Bs_s = As_s + STAGE_B / 2;

    auto issue_stage = [&](int kt, int s) {
        const float* ag = Ag + kt * 16;
        const float* bg = Bg + kt * 16;
        uint32_t as = As_s + s * STAGE_B;
        uint32_t bs = Bs_s + s * STAGE_B;
        cp16(as, ag);      cp16(as + 16, ag + 4);
        cp16(bs, bg);      cp16(bs + 16, bg + 4);
        cp_commit();
    };

    float acc[4][4][4];
#pragma unroll
    for (int i = 0; i < 4; i++)
#pragma unroll
        for (int j = 0; j < 4; j++)
#pragma unroll
            for (int r = 0; r < 4; r++) acc[i][j][r] = 0.f;

    int niter = K / 16;
    issue_stage(0, 0);
    issue_stage(1, 1);
    issue_stage(2, 2);

    for (int kt = 0; kt < niter; ++kt) {
        int rem = niter - 1 - kt;
        if (rem >= 2)      cp_wait<2>();
        else if (rem == 1) cp_wait<1>();
        else               cp_wait<0>();
        __syncthreads();

        if (kt + 3 < niter) issue_stage(kt + 3, (kt + 3) & 3);

        const float* Ab = smf + (size_t)(kt & 3) * (STAGE_B / 4);
        const float* Bb = Ab + STAGE_B / 8;
#pragma unroll
        for (int ks = 0; ks < 16; ks += 8) {
            uint32_t af[4][4];
#pragma unroll
            for (int mt = 0; mt < 4; ++mt) {
                int mr = wm * 64 + mt * 16 + grp;
                af[mt][0] = __float_as_uint(Ab[mr * GSTR + ks + tig]);
                af[mt][1] = __float_as_uint(Ab[(mr + 8) * GSTR + ks + tig]);
                af[mt][2] = __float_as_uint(Ab[mr * GSTR + ks + tig + 4]);
                af[mt][3] = __float_as_uint(Ab[(mr + 8) * GSTR + ks + tig + 4]);
            }
            uint32_t bf[4][2];
#pragma unroll
            for (int nt = 0; nt < 4; ++nt) {
                int nc = wn * 32 + nt * 8 + grp;
                bf[nt][0] = __float_as_uint(Bb[nc * GSTR + ks + tig]);
                bf[nt][1] = __float_as_uint(Bb[nc * GSTR + ks + tig + 4]);
            }
#pragma unroll
            for (int mt = 0; mt < 4; ++mt)
#pragma unroll
                for (int nt = 0; nt < 4; ++nt)
                    mma_tf32(acc[mt][nt], af[mt], bf[nt]);
        }
    }

#pragma unroll
    for (int mt = 0; mt < 4; ++mt) {
#pragma unroll
        for (int nt = 0; nt < 4; ++nt) {
            int row = m0 + wm * 64 + mt * 16 + grp;
            int col = n0 + wn * 32 + nt * 8 + 2 * tig;
            *(float2*)(C + (size_t)row * N + col) =
                make_float2(acc[mt][nt][0], acc[mt][nt][1]);
            *(float2*)(C + (size_t)(row + 8) * N + col) =
                make_float2(acc[mt][nt][2], acc[mt][nt][3]);
        }
    }
}

// ----------------------------------------------------------------------------
// Tensor-core flash attention (tf32 mma), occupancy-2 (round-10 WIN version).
// Only change: epilogue stores tf32-rounded vals (numerically identical to
// GEMM2's former load-convert; enables cp.async GEMM2).
// ----------------------------------------------------------------------------
#define PSTR 68
#define VSTR 72

__global__ __launch_bounds__(256, 2) void attn_tc(
    const float* __restrict__ qkv, float* __restrict__ vals)
{
    extern __shared__ float sm[];
    float* Pbuf = sm;                              // [128][PSTR]
    float* Ksm  = sm + 64 * PSTR;                  // rows 64..127 of Pbuf
    float* Vsm  = sm + 128 * PSTR;                 // [64][VSTR]
    float* Qsm  = sm + 128 * PSTR + 64 * VSTR;     // [128][PSTR]

    int tid  = threadIdx.x;
    int lane = tid & 31;
    int warp = tid >> 5;
    int grp  = lane >> 2;
    int tig  = lane & 3;

    int qb = blockIdx.x;
    int h  = blockIdx.y;
    int b  = blockIdx.z;

    const float* base = qkv + (size_t)b * S_ * QKV_N + h * (3 * HD_);
    const float* qg = base;
    const float* kg = base + HD_;
    const float* vg = base + 2 * HD_;
    int q0 = qb * 128;
    int r0 = warp * 16 + grp;

#pragma unroll
    for (int p = 0; p < 8; ++p) {
        int idx = tid + p * 256;
        int row = idx >> 4;
        int c4  = idx & 15;
        float4 v = *(const float4*)(qg + (size_t)(q0 + row) * QKV_N + c4 * 4);
        float4 t;
        t.x = to_tf32(v.x * 0.125f);
        t.y = to_tf32(v.y * 0.125f);
        t.z = to_tf32(v.z * 0.125f);
        t.w = to_tf32(v.w * 0.125f);
        *(float4*)(Qsm + row * PSTR + c4 * 4) = t;
    }

    float m_i[2] = {-1e30f, -1e30f};
    float l_i[2] = {0.f, 0.f};
    float oacc[8][4];
#pragma unroll
    for (int nt = 0; nt < 8; ++nt)
#pragma unroll
        for (int r = 0; r < 4; ++r) oacc[nt][r] = 0.f;

    __syncthreads();

    for (int kt = 0; kt < S_; kt += 64) {
#pragma unroll
        for (int p = 0; p < 4; ++p) {
            int idx = tid + p * 256;
            int row = idx >> 4;
            int c4  = idx & 15;
            float4 v = *(const float4*)(kg + (size_t)(kt + row) * QKV_N + c4 * 4);
            float4 t;
            t.x = to_tf32(v.x); t.y = to_tf32(v.y);
            t.z = to_tf32(v.z); t.w = to_tf32(v.w);
            *(float4*)(Ksm + row * PSTR + c4 * 4) = t;
            float4 w = *(const float4*)(vg + (size_t)(kt + row) * QKV_N + c4 * 4);
            float4 u;
            u.x = to_tf32(w.x); u.y = to_tf32(w.y);
            u.z = to_tf32(w.z); u.w = to_tf32(w.w);
            *(float4*)(Vsm + row * VSTR + c4 * 4) = u;
        }
        __syncthreads();

        float sacc[8][4];
#pragma unroll
        for (int nt = 0; nt < 8; ++nt)
#pragma unroll
            for (int r = 0; r < 4; ++r) sacc[nt][r] = 0.f;

#pragma unroll
        for (int ks = 0; ks < 8; ++ks) {
            uint32_t qf[4];
            qf[0] = __float_as_uint(Qsm[r0 * PSTR + 8 * ks + tig]);
            qf[1] = __float_as_uint(Qsm[(r0 + 8) * PSTR + 8 * ks + tig]);
            qf[2] = __float_as_uint(Qsm[r0 * PSTR + 8 * ks + tig + 4]);
            qf[3] = __float_as_uint(Qsm[(r0 + 8) * PSTR + 8 * ks + tig + 4]);
            uint32_t bf[8][2];
#pragma unroll
            for (int nt = 0; nt < 8; ++nt) {
                bf[nt][0] = __float_as_uint(Ksm[(nt * 8 + grp) * PSTR + 8 * ks + tig]);
                bf[nt][1] = __float_as_uint(Ksm[(nt * 8 + grp) * PSTR + 8 * ks + tig + 4]);
            }
#pragma unroll
            for (int nt = 0; nt < 8; ++nt)
                mma_tf32(sacc[nt], qf, bf[nt]);
        }
        __syncthreads();

        float mx0 = -1e30f, mx1 = -1e30f;
#pragma unroll
        for (int nt = 0; nt < 8; ++nt) {
            mx0 = fmaxf(mx0, fmaxf(sacc[nt][0], sacc[nt][1]));
            mx1 = fmaxf(mx1, fmaxf(sacc[nt][2], sacc[nt][3]));
        }
        mx0 = fmaxf(mx0, __shfl_xor_sync(0xffffffffu, mx0, 1));
        mx0 = fmaxf(mx0, __shfl_xor_sync(0xffffffffu, mx0, 2));
        mx1 = fmaxf(mx1, __shfl_xor_sync(0xffffffffu, mx1, 1));
        mx1 = fmaxf(mx1, __shfl_xor_sync(0xffffffffu, mx1, 2));

        float mn0 = fmaxf(m_i[0], mx0);
        float mn1 = fmaxf(m_i[1], mx1);
        float f0 = __expf(m_i[0] - mn0);
        float f1 = __expf(m_i[1] - mn1);
        m_i[0] = mn0; m_i[1] = mn1;

        float rs0 = 0.f, rs1 = 0.f;
#pragma unroll
        for (int nt = 0; nt < 8; ++nt) {
            float p0 = __expf(sacc[nt][0] - mn0);
            float p1 = __expf(sacc[nt][1] - mn0);
            float p2 = __expf(sacc[nt][2] - mn1);
            float p3 = __expf(sacc[nt][3] - mn1);
            rs0 += p0 + p1;
            rs1 += p2 + p3;
            *(float2*)(Pbuf + r0 * PSTR + nt * 8 + 2 * tig) =
                make_float2(to_tf32(p0), to_tf32(p1));
            *(float2*)(Pbuf + (r0 + 8) * PSTR + nt * 8 + 2 * tig) =
                make_float2(to_tf32(p2), to_tf32(p3));
        }
        rs0 += __shfl_xor_sync(0xffffffffu, rs0, 1);
        rs0 += __shfl_xor_sync(0xffffffffu, rs0, 2);
        rs1 += __shfl_xor_sync(0xffffffffu, rs1, 1);
        rs1 += __shfl_xor_sync(0xffffffffu, rs1, 2);
        l_i[0] = l_i[0] * f0 + rs0;
        l_i[1] = l_i[1] * f1 + rs1;

#pragma unroll
        for (int nt = 0; nt < 8; ++nt) {
            oacc[nt][0] *= f0; oacc[nt][1] *= f0;
            oacc[nt][2] *= f1; oacc[nt][3] *= f1;
        }
        __syncthreads();

#pragma unroll
        for (int ks = 0; ks < 8; ++ks) {
            uint32_t af[4];
            af[0] = __float_as_uint(Pbuf[r0 * PSTR + 8 * ks + tig]);
            af[1] = __float_as_uint(Pbuf[(r0 + 8) * PSTR + 8 * ks + tig]);
            af[2] = __float_as_uint(Pbuf[r0 * PSTR + 8 * ks + tig + 4]);
            af[3] = __float_as_uint(Pbuf[(r0 + 8) * PSTR + 8 * ks + tig + 4]);
#pragma unroll
            for (int nt = 0; nt < 8; ++nt) {
                uint32_t bf[2];
                bf[0] = __float_as_uint(Vsm[(8 * ks + tig) * VSTR + nt * 8 + grp]);
                bf[1] = __float_as_uint(Vsm[(8 * ks + tig + 4) * VSTR + nt * 8 + grp]);
                mma_tf32(oacc[nt], af, bf);
            }
        }
        __syncthreads();
    }

    // Epilogue: normalize + tf32-round (matches former GEMM2 load-convert)
    float inv0 = 1.f / l_i[0];
    float inv1 = 1.f / l_i[1];
    size_t row0 = (size_t)b * S_ + q0 + r0;
#pragma unroll
    for (int nt = 0; nt < 8; ++nt) {
        int col = h * HD_ + nt * 8 + 2 * tig;
        *(float2*)(vals + row0 * E_ + col) =
            make_float2(to_tf32(oacc[nt][0] * inv0), to_tf32(oacc[nt][1] * inv0));
        *(float2*)(vals + (row0 + 8) * E_ + col) =
            make_float2(to_tf32(oacc[nt][2] * inv1), to_tf32(oacc[nt][3] * inv1));
    }
}

// ----------------------------------------------------------------------------
// Launch
// ----------------------------------------------------------------------------
#define ATTN_SMEM ((128 * PSTR + 64 * VSTR + 128 * PSTR) * 4)   // 88064 bytes

extern "C" void kernel_launch(void* const* d_in, const int* in_sizes, int n_in,
                              void* d_out, int out_size)
{
    (void)in_sizes; (void)n_in; (void)out_size;
    const float* x     = (const float*)d_in[0];
    const float* qkv_w = (const float*)d_in[1];
    const float* o_w   = (const float*)d_in[2];
    float* out = (float*)d_out;

    static float *qkv_buf = nullptr, *vals_buf = nullptr;
    static float *xc = nullptr, *wc = nullptr, *oc = nullptr;
    if (qkv_buf == nullptr) {
        cudaGetSymbolAddress((void**)&qkv_buf, g_qkv);
        cudaGetSymbolAddress((void**)&vals_buf, g_vals);
        cudaGetSymbolAddress((void**)&xc, g_xc);
        cudaGetSymbolAddress((void**)&wc, g_wc);
        cudaGetSymbolAddress((void**)&oc, g_oc);
        cudaFuncSetAttribute(attn_tc,
                             cudaFuncAttributeMaxDynamicSharedMemorySize,
                             ATTN_SMEM);
        cudaFuncSetAttribute(gemm_ca,
                             cudaFuncAttributeMaxDynamicSharedMemorySize,
                             GEMM_SMEM);
    }

    dim3 blk(256);
    // 0) Pre-round operands to tf32-valued fp32
    {
        int n4x = M_TOT * D_ / 4;
        int n4w = QKV_N * D_ / 4;
        int n4o = E_ * D_ / 4;
        cvt_tf32_kernel<<<(n4x + 255) / 256, blk>>>(x, xc, n4x);
        cvt_tf32_kernel<<<(n4w + 255) / 256, blk>>>(qkv_w, wc, n4w);
        cvt_tf32_kernel<<<(n4o + 255) / 256, blk>>>(o_w, oc, n4o);
    }
    // 1) qkv = x @ qkv_w^T
    gemm_ca<<<dim3(QKV_N / 128, M_TOT / 128), blk, GEMM_SMEM>>>(
        xc, wc, qkv_buf, M_TOT, QKV_N, D_);
    // 2) attention -> vals (tf32-rounded)
    attn_tc<<<dim3(S_ / 128, NH_, B_), blk, ATTN_SMEM>>>(qkv_buf, vals_buf);
    // 3) out = vals @ o_w^T
    gemm_ca<<<dim3(E_ / 128, M_TOT / 128), blk, GEMM_SMEM>>>(
        vals_buf, oc, out, M_TOT, E_, D_);
}

// round 12
// speedup vs baseline: 1.2062x; 1.0276x over previous
#include <cuda_runtime.h>
#include <math.h>
#include <stdint.h>

// Problem constants
#define B_   4
#define S_   2048
#define D_   1024
#define E_   1024
#define NH_  16
#define HD_  64
#define QKV_N (3 * E_)       // 3072
#define M_TOT (B_ * S_)      // 8192

// Scratch (device globals — allocation-free per harness rules)
__device__ float g_qkv[(size_t)M_TOT * QKV_N];   // [8192, 3072] tf32-valued
__device__ float g_vals[(size_t)M_TOT * E_];     // [8192, 1024] tf32-valued
__device__ float g_xc[(size_t)M_TOT * D_];       // x, tf32-rounded
__device__ float g_wc[(size_t)QKV_N * D_];       // qkv_w, tf32-rounded
__device__ float g_oc[(size_t)E_ * D_];          // o_w, tf32-rounded

// ----------------------------------------------------------------------------
// tf32 helpers
// ----------------------------------------------------------------------------
__device__ __forceinline__ float to_tf32(float x) {
    uint32_t u;
    asm("cvt.rna.tf32.f32 %0, %1;" : "=r"(u) : "f"(x));
    return __uint_as_float(u);
}

__device__ __forceinline__ void mma_tf32(float* c, const uint32_t* a,
                                         const uint32_t* b) {
    asm volatile(
        "mma.sync.aligned.m16n8k8.row.col.f32.tf32.tf32.f32 "
        "{%0,%1,%2,%3},{%4,%5,%6,%7},{%8,%9},{%0,%1,%2,%3};"
        : "+f"(c[0]), "+f"(c[1]), "+f"(c[2]), "+f"(c[3])
        : "r"(a[0]), "r"(a[1]), "r"(a[2]), "r"(a[3]),
          "r"(b[0]), "r"(b[1]));
}

__device__ __forceinline__ void cp16(uint32_t saddr, const void* g) {
    asm volatile("cp.async.cg.shared.global [%0], [%1], 16;"
                 :: "r"(saddr), "l"(g) : "memory");
}
__device__ __forceinline__ void cp_commit() {
    asm volatile("cp.async.commit_group;" ::: "memory");
}
template <int N>
__device__ __forceinline__ void cp_wait() {
    asm volatile("cp.async.wait_group %0;" :: "n"(N) : "memory");
}

// ----------------------------------------------------------------------------
// Pre-round a tensor to tf32-valued fp32 (RNA), 4 elems/thread.
// ----------------------------------------------------------------------------
__global__ __launch_bounds__(256) void cvt_tf32_kernel(
    const float* __restrict__ in, float* __restrict__ out, int n4)
{
    int i = blockIdx.x * blockDim.x + threadIdx.x;
    if (i < n4) {
        float4 v = ((const float4*)in)[i];
        float4 t;
        t.x = to_tf32(v.x); t.y = to_tf32(v.y);
        t.z = to_tf32(v.z); t.w = to_tf32(v.w);
        ((float4*)out)[i] = t;
    }
}

// ----------------------------------------------------------------------------
// cp.async tf32 GEMM (round-11 WIN version): C = A[M,K] @ B[N,K]^T.
// roundC != 0 -> store tf32-rounded C (for qkv feeding attention).
// ----------------------------------------------------------------------------
#define GSTR 20
#define STAGE_B (2 * 128 * GSTR * 4)            // 20480 bytes
#define GEMM_SMEM (4 * STAGE_B)                  // 81920 bytes

__global__ __launch_bounds__(256, 2) void gemm_ca(
    const float* __restrict__ A, const float* __restrict__ Bm,
    float* __restrict__ C, int M, int N, int K, int roundC)
{
    extern __shared__ float smf[];
    uint32_t sb = (uint32_t)__cvta_generic_to_shared(smf);

    int tid  = threadIdx.x;
    int lane = tid & 31;
    int warp = tid >> 5;
    int wm = warp & 1;
    int wn = warp >> 1;
    int tig = lane & 3;
    int grp = lane >> 2;

    int m0 = blockIdx.y * 128;
    int n0 = blockIdx.x * 128;

    int lrow = tid >> 1;
    int cb   = (tid & 1) * 2;
    const float* Ag = A  + (size_t)(m0 + lrow) * K + cb * 4;
    const float* Bg = Bm + (size_t)(n0 + lrow) * K + cb * 4;
    uint32_t As_s = sb + lrow * (GSTR * 4) + cb * 16;
    uint32_t Bs_s = As_s + STAGE_B / 2;

    auto issue_stage = [&](int kt, int s) {
        const float* ag = Ag + kt * 16;
        const float* bg = Bg + kt * 16;
        uint32_t as = As_s + s * STAGE_B;
        uint32_t bs = Bs_s + s * STAGE_B;
        cp16(as, ag);      cp16(as + 16, ag + 4);
        cp16(bs, bg);      cp16(bs + 16, bg + 4);
        cp_commit();
    };

    float acc[4][4][4];
#pragma unroll
    for (int i = 0; i < 4; i++)
#pragma unroll
        for (int j = 0; j < 4; j++)
#pragma unroll
            for (int r = 0; r < 4; r++) acc[i][j][r] = 0.f;

    int niter = K / 16;
    issue_stage(0, 0);
    issue_stage(1, 1);
    issue_stage(2, 2);

    for (int kt = 0; kt < niter; ++kt) {
        int rem = niter - 1 - kt;
        if (rem >= 2)      cp_wait<2>();
        else if (rem == 1) cp_wait<1>();
        else               cp_wait<0>();
        __syncthreads();

        if (kt + 3 < niter) issue_stage(kt + 3, (kt + 3) & 3);

        const float* Ab = smf + (size_t)(kt & 3) * (STAGE_B / 4);
        const float* Bb = Ab + STAGE_B / 8;
#pragma unroll
        for (int ks = 0; ks < 16; ks += 8) {
            uint32_t af[4][4];
#pragma unroll
            for (int mt = 0; mt < 4; ++mt) {
                int mr = wm * 64 + mt * 16 + grp;
                af[mt][0] = __float_as_uint(Ab[mr * GSTR + ks + tig]);
                af[mt][1] = __float_as_uint(Ab[(mr + 8) * GSTR + ks + tig]);
                af[mt][2] = __float_as_uint(Ab[mr * GSTR + ks + tig + 4]);
                af[mt][3] = __float_as_uint(Ab[(mr + 8) * GSTR + ks + tig + 4]);
            }
            uint32_t bf[4][2];
#pragma unroll
            for (int nt = 0; nt < 4; ++nt) {
                int nc = wn * 32 + nt * 8 + grp;
                bf[nt][0] = __float_as_uint(Bb[nc * GSTR + ks + tig]);
                bf[nt][1] = __float_as_uint(Bb[nc * GSTR + ks + tig + 4]);
            }
#pragma unroll
            for (int mt = 0; mt < 4; ++mt)
#pragma unroll
                for (int nt = 0; nt < 4; ++nt)
                    mma_tf32(acc[mt][nt], af[mt], bf[nt]);
        }
    }

#pragma unroll
    for (int mt = 0; mt < 4; ++mt) {
#pragma unroll
        for (int nt = 0; nt < 4; ++nt) {
            int row = m0 + wm * 64 + mt * 16 + grp;
            int col = n0 + wn * 32 + nt * 8 + 2 * tig;
            float v0 = acc[mt][nt][0], v1 = acc[mt][nt][1];
            float v2 = acc[mt][nt][2], v3 = acc[mt][nt][3];
            if (roundC) {
                v0 = to_tf32(v0); v1 = to_tf32(v1);
                v2 = to_tf32(v2); v3 = to_tf32(v3);
            }
            *(float2*)(C + (size_t)row * N + col) = make_float2(v0, v1);
            *(float2*)(C + (size_t)(row + 8) * N + col) = make_float2(v2, v3);
        }
    }
}

// ----------------------------------------------------------------------------
// Tensor-core flash attention, cp.async pipelined, occupancy-2.
// qkv MUST be tf32-valued (GEMM1 rounds its output). Q unscaled in smem;
// the 1/8 scale is applied to S after the mma (exact power-of-two).
// Smem 103KB (de-aliased): Qsm[128][68] + Ksm[64][68] + Vsm[64][72] +
// Pbuf[128][68]. K(t+1)/V(t+1) prefetched via cp.async during compute.
// ----------------------------------------------------------------------------
#define PSTR 68
#define VSTR 72
#define ATTN_SMEM ((128 * PSTR + 64 * PSTR + 64 * VSTR + 128 * PSTR) * 4)

__global__ __launch_bounds__(256, 2) void attn_tc(
    const float* __restrict__ qkv, float* __restrict__ vals)
{
    extern __shared__ float sm[];
    float* Qsm  = sm;                                    // [128][PSTR]
    float* Ksm  = sm + 128 * PSTR;                       // [64][PSTR]
    float* Vsm  = sm + 128 * PSTR + 64 * PSTR;           // [64][VSTR]
    float* Pbuf = sm + 128 * PSTR + 64 * PSTR + 64 * VSTR; // [128][PSTR]

    uint32_t sb = (uint32_t)__cvta_generic_to_shared(sm);
    uint32_t Qs_b = sb;
    uint32_t Ks_b = sb + 128 * PSTR * 4;
    uint32_t Vs_b = Ks_b + 64 * PSTR * 4;

    int tid  = threadIdx.x;
    int lane = tid & 31;
    int warp = tid >> 5;
    int grp  = lane >> 2;
    int tig  = lane & 3;

    int qb = blockIdx.x;
    int h  = blockIdx.y;
    int b  = blockIdx.z;

    const float* base = qkv + (size_t)b * S_ * QKV_N + h * (3 * HD_);
    const float* qg = base;
    const float* kg = base + HD_;
    const float* vg = base + 2 * HD_;
    int q0 = qb * 128;
    int r0 = warp * 16 + grp;

    // cp.async issue helpers: tile rows x 64 floats, 16B chunks.
    auto issue_q = [&]() {
#pragma unroll
        for (int p = 0; p < 8; ++p) {
            int idx = tid + p * 256;        // 0..2047
            int row = idx >> 4;
            int c   = idx & 15;
            cp16(Qs_b + (row * PSTR + c * 4) * 4,
                 qg + (size_t)(q0 + row) * QKV_N + c * 4);
        }
        cp_commit();
    };
    auto issue_k = [&](int kt) {
#pragma unroll
        for (int p = 0; p < 4; ++p) {
            int idx = tid + p * 256;        // 0..1023
            int row = idx >> 4;
            int c   = idx & 15;
            cp16(Ks_b + (row * PSTR + c * 4) * 4,
                 kg + (size_t)(kt + row) * QKV_N + c * 4);
        }
        cp_commit();
    };
    auto issue_v = [&](int kt) {
#pragma unroll
        for (int p = 0; p < 4; ++p) {
            int idx = tid + p * 256;
            int row = idx >> 4;
            int c   = idx & 15;
            cp16(Vs_b + (row * VSTR + c * 4) * 4,
                 vg + (size_t)(kt + row) * QKV_N + c * 4);
        }
        cp_commit();
    };

    issue_q();        // group: Q
    issue_k(0);       // group: K0
    issue_v(0);       // group: V0

    float m_i[2] = {-1e30f, -1e30f};
    float l_i[2] = {0.f, 0.f};
    float oacc[8][4];
#pragma unroll
    for (int nt = 0; nt < 8; ++nt)
#pragma unroll
        for (int r = 0; r < 4; ++r) oacc[nt][r] = 0.f;

    for (int kt = 0; kt < S_; kt += 64) {
        bool last = (kt + 64 >= S_);

        // ---- wait K(t) (and Q on first iter): <=1 group outstanding ----
        cp_wait<1>();
        __syncthreads();

        // ---- S = Q @ K^T ----
        float sacc[8][4];
#pragma unroll
        for (int nt = 0; nt < 8; ++nt)
#pragma unroll
            for (int r = 0; r < 4; ++r) sacc[nt][r] = 0.f;

#pragma unroll
        for (int ks = 0; ks < 8; ++ks) {
            uint32_t qf[4];
            qf[0] = __float_as_uint(Qsm[r0 * PSTR + 8 * ks + tig]);
            qf[1] = __float_as_uint(Qsm[(r0 + 8) * PSTR + 8 * ks + tig]);
            qf[2] = __float_as_uint(Qsm[r0 * PSTR + 8 * ks + tig + 4]);
            qf[3] = __float_as_uint(Qsm[(r0 + 8) * PSTR + 8 * ks + tig + 4]);
            uint32_t bf[8][2];
#pragma unroll
            for (int nt = 0; nt < 8; ++nt) {
                bf[nt][0] = __float_as_uint(Ksm[(nt * 8 + grp) * PSTR + 8 * ks + tig]);
                bf[nt][1] = __float_as_uint(Ksm[(nt * 8 + grp) * PSTR + 8 * ks + tig + 4]);
            }
#pragma unroll
            for (int nt = 0; nt < 8; ++nt)
                mma_tf32(sacc[nt], qf, bf[nt]);
        }
        __syncthreads();            // K reads done
        if (!last) issue_k(kt + 64);   // prefetch K(t+1) during softmax+PV

        // ---- Online softmax (scale 1/8 folded in here) ----
        float mx0 = -1e30f, mx1 = -1e30f;
#pragma unroll
        for (int nt = 0; nt < 8; ++nt) {
#pragma unroll
            for (int r = 0; r < 4; ++r) sacc[nt][r] *= 0.125f;
            mx0 = fmaxf(mx0, fmaxf(sacc[nt][0], sacc[nt][1]));
            mx1 = fmaxf(mx1, fmaxf(sacc[nt][2], sacc[nt][3]));
        }
        mx0 = fmaxf(mx0, __shfl_xor_sync(0xffffffffu, mx0, 1));
        mx0 = fmaxf(mx0, __shfl_xor_sync(0xffffffffu, mx0, 2));
        mx1 = fmaxf(mx1, __shfl_xor_sync(0xffffffffu, mx1, 1));
        mx1 = fmaxf(mx1, __shfl_xor_sync(0xffffffffu, mx1, 2));

        float mn0 = fmaxf(m_i[0], mx0);
        float mn1 = fmaxf(m_i[1], mx1);
        float f0 = __expf(m_i[0] - mn0);
        float f1 = __expf(m_i[1] - mn1);
        m_i[0] = mn0; m_i[1] = mn1;

        float rs0 = 0.f, rs1 = 0.f;
#pragma unroll
        for (int nt = 0; nt < 8; ++nt) {
            float p0 = __expf(sacc[nt][0] - mn0);
            float p1 = __expf(sacc[nt][1] - mn0);
            float p2 = __expf(sacc[nt][2] - mn1);
            float p3 = __expf(sacc[nt][3] - mn1);
            rs0 += p0 + p1;
            rs1 += p2 + p3;
            *(float2*)(Pbuf + r0 * PSTR + nt * 8 + 2 * tig) =
                make_float2(to_tf32(p0), to_tf32(p1));
            *(float2*)(Pbuf + (r0 + 8) * PSTR + nt * 8 + 2 * tig) =
                make_float2(to_tf32(p2), to_tf32(p3));
        }
        rs0 += __shfl_xor_sync(0xffffffffu, rs0, 1);
        rs0 += __shfl_xor_sync(0xffffffffu, rs0, 2);
        rs1 += __shfl_xor_sync(0xffffffffu, rs1, 1);
        rs1 += __shfl_xor_sync(0xffffffffu, rs1, 2);
        l_i[0] = l_i[0] * f0 + rs0;
        l_i[1] = l_i[1] * f1 + rs1;

#pragma unroll
        for (int nt = 0; nt < 8; ++nt) {
            oacc[nt][0] *= f0; oacc[nt][1] *= f0;
            oacc[nt][2] *= f1; oacc[nt][3] *= f1;
        }

        // ---- wait V(t): pending = [V(t), K(t+1)] -> <=1 outstanding;
        //      on last iter pending = [V(t)] only -> drain fully ----
        if (!last) cp_wait<1>(); else cp_wait<0>();
        __syncthreads();            // P visible + V(t) arrived

        // ---- O += P @ V ----
#pragma unroll
        for (int ks = 0; ks < 8; ++ks) {
            uint32_t af[4];
            af[0] = __float_as_uint(Pbuf[r0 * PSTR + 8 * ks + tig]);
            af[1] = __float_as_uint(Pbuf[(r0 + 8) * PSTR + 8 * ks + tig]);
            af[2] = __float_as_uint(Pbuf[r0 * PSTR + 8 * ks + tig + 4]);
            af[3] = __float_as_uint(Pbuf[(r0 + 8) * PSTR + 8 * ks + tig + 4]);
#pragma unroll
            for (int nt = 0; nt < 8; ++nt) {
                uint32_t bf[2];
                bf[0] = __float_as_uint(Vsm[(8 * ks + tig) * VSTR + nt * 8 + grp]);
                bf[1] = __float_as_uint(Vsm[(8 * ks + tig + 4) * VSTR + nt * 8 + grp]);
                mma_tf32(oacc[nt], af, bf);
            }
        }
        __syncthreads();            // V reads done
        if (!last) issue_v(kt + 64);   // prefetch V(t+1)
    }

    // ---- Epilogue: normalize + tf32-round (feeds GEMM2's cp.async path) ----
    float inv0 = 1.f / l_i[0];
    float inv1 = 1.f / l_i[1];
    size_t row0 = (size_t)b * S_ + q0 + r0;
#pragma unroll
    for (int nt = 0; nt < 8; ++nt) {
        int col = h * HD_ + nt * 8 + 2 * tig;
        *(float2*)(vals + row0 * E_ + col) =
            make_float2(to_tf32(oacc[nt][0] * inv0), to_tf32(oacc[nt][1] * inv0));
        *(float2*)(vals + (row0 + 8) * E_ + col) =
            make_float2(to_tf32(oacc[nt][2] * inv1), to_tf32(oacc[nt][3] * inv1));
    }
}

// ----------------------------------------------------------------------------
// Launch
// ----------------------------------------------------------------------------
extern "C" void kernel_launch(void* const* d_in, const int* in_sizes, int n_in,
                              void* d_out, int out_size)
{
    (void)in_sizes; (void)n_in; (void)out_size;
    const float* x     = (const float*)d_in[0];
    const float* qkv_w = (const float*)d_in[1];
    const float* o_w   = (const float*)d_in[2];
    float* out = (float*)d_out;

    static float *qkv_buf = nullptr, *vals_buf = nullptr;
    static float *xc = nullptr, *wc = nullptr, *oc = nullptr;
    if (qkv_buf == nullptr) {
        cudaGetSymbolAddress((void**)&qkv_buf, g_qkv);
        cudaGetSymbolAddress((void**)&vals_buf, g_vals);
        cudaGetSymbolAddress((void**)&xc, g_xc);
        cudaGetSymbolAddress((void**)&wc, g_wc);
        cudaGetSymbolAddress((void**)&oc, g_oc);
        cudaFuncSetAttribute(attn_tc,
                             cudaFuncAttributeMaxDynamicSharedMemorySize,
                             ATTN_SMEM);
        cudaFuncSetAttribute(gemm_ca,
                             cudaFuncAttributeMaxDynamicSharedMemorySize,
                             GEMM_SMEM);
    }

    dim3 blk(256);
    // 0) Pre-round operands to tf32-valued fp32
    {
        int n4x = M_TOT * D_ / 4;
        int n4w = QKV_N * D_ / 4;
        int n4o = E_ * D_ / 4;
        cvt_tf32_kernel<<<(n4x + 255) / 256, blk>>>(x, xc, n4x);
        cvt_tf32_kernel<<<(n4w + 255) / 256, blk>>>(qkv_w, wc, n4w);
        cvt_tf32_kernel<<<(n4o + 255) / 256, blk>>>(o_w, oc, n4o);
    }
    // 1) qkv = x @ qkv_w^T  (output rounded to tf32 values)
    gemm_ca<<<dim3(QKV_N / 128, M_TOT / 128), blk, GEMM_SMEM>>>(
        xc, wc, qkv_buf, M_TOT, QKV_N, D_, 1);
    // 2) attention -> vals (tf32-rounded)
    attn_tc<<<dim3(S_ / 128, NH_, B_), blk, ATTN_SMEM>>>(qkv_buf, vals_buf);
    // 3) out = vals @ o_w^T  (full fp32 output)
    gemm_ca<<<dim3(E_ / 128, M_TOT / 128), blk, GEMM_SMEM>>>(
        vals_buf, oc, out, M_TOT, E_, D_, 0);
}

// round 13
// speedup vs baseline: 1.2739x; 1.0561x over previous
#include <cuda_runtime.h>
#include <math.h>
#include <stdint.h>

// Problem constants
#define B_   4
#define S_   2048
#define D_   1024
#define E_   1024
#define NH_  16
#define HD_  64
#define QKV_N (3 * E_)       // 3072
#define M_TOT (B_ * S_)      // 8192

// Scratch (device globals — allocation-free per harness rules)
__device__ float g_qkv[(size_t)M_TOT * QKV_N];   // [8192, 3072] tf32-valued
__device__ float g_vals[(size_t)M_TOT * E_];     // [8192, 1024] tf32-valued
__device__ float g_xc[(size_t)M_TOT * D_];       // x, tf32-rounded
__device__ float g_wc[(size_t)QKV_N * D_];       // qkv_w, tf32-rounded
__device__ float g_oc[(size_t)E_ * D_];          // o_w, tf32-rounded

// ----------------------------------------------------------------------------
// tf32 / mma / cp.async / ldmatrix helpers
// ----------------------------------------------------------------------------
__device__ __forceinline__ float to_tf32(float x) {
    uint32_t u;
    asm("cvt.rna.tf32.f32 %0, %1;" : "=r"(u) : "f"(x));
    return __uint_as_float(u);
}

__device__ __forceinline__ void mma_tf32(float* c, const uint32_t* a,
                                         const uint32_t* b) {
    asm volatile(
        "mma.sync.aligned.m16n8k8.row.col.f32.tf32.tf32.f32 "
        "{%0,%1,%2,%3},{%4,%5,%6,%7},{%8,%9},{%0,%1,%2,%3};"
        : "+f"(c[0]), "+f"(c[1]), "+f"(c[2]), "+f"(c[3])
        : "r"(a[0]), "r"(a[1]), "r"(a[2]), "r"(a[3]),
          "r"(b[0]), "r"(b[1]));
}

__device__ __forceinline__ void cp16(uint32_t saddr, const void* g) {
    asm volatile("cp.async.cg.shared.global [%0], [%1], 16;"
                 :: "r"(saddr), "l"(g) : "memory");
}
__device__ __forceinline__ void cp_commit() {
    asm volatile("cp.async.commit_group;" ::: "memory");
}
template <int N>
__device__ __forceinline__ void cp_wait() {
    asm volatile("cp.async.wait_group %0;" :: "n"(N) : "memory");
}

__device__ __forceinline__ void ldsm_x4(uint32_t* r, uint32_t addr) {
    asm volatile(
        "ldmatrix.sync.aligned.m8n8.x4.shared.b16 {%0,%1,%2,%3}, [%4];"
        : "=r"(r[0]), "=r"(r[1]), "=r"(r[2]), "=r"(r[3])
        : "r"(addr));
}

// ----------------------------------------------------------------------------
// Pre-round a tensor to tf32-valued fp32 (RNA), 4 elems/thread.
// ----------------------------------------------------------------------------
__global__ __launch_bounds__(256) void cvt_tf32_kernel(
    const float* __restrict__ in, float* __restrict__ out, int n4)
{
    int i = blockIdx.x * blockDim.x + threadIdx.x;
    if (i < n4) {
        float4 v = ((const float4*)in)[i];
        float4 t;
        t.x = to_tf32(v.x); t.y = to_tf32(v.y);
        t.z = to_tf32(v.z); t.w = to_tf32(v.w);
        ((float4*)out)[i] = t;
    }
}

// ----------------------------------------------------------------------------
// cp.async + ldmatrix tf32 GEMM: C = A[M,K] @ B[N,K]^T.
// Operands must be tf32-valued fp32. 128x128 tile, BK=16, 4-stage cp.async
// pipeline. Fragments loaded via ldmatrix.x4 (6 LDSM per ks-step vs 24 LDS):
//   A frag (a0..a3): lane -> row mr_base+(lane&15), kcol ks+4*(lane>>4)
//   B frag pairs:    lane -> n nc_base+(lane&7)+8*(lane>>4), kcol ks+4*((lane>>3)&1)
// GSTR=20 float stride: each 8-address LDSM phase covers all 32 banks.
// roundC != 0 -> store tf32-rounded C.
// ----------------------------------------------------------------------------
#define GSTR 20
#define STAGE_B (2 * 128 * GSTR * 4)            // 20480 bytes
#define GEMM_SMEM (4 * STAGE_B)                  // 81920 bytes

__global__ __launch_bounds__(256, 2) void gemm_ca(
    const float* __restrict__ A, const float* __restrict__ Bm,
    float* __restrict__ C, int M, int N, int K, int roundC)
{
    extern __shared__ float smf[];
    uint32_t sb = (uint32_t)__cvta_generic_to_shared(smf);

    int tid  = threadIdx.x;
    int lane = tid & 31;
    int warp = tid >> 5;
    int wm = warp & 1;
    int wn = warp >> 1;
    int tig = lane & 3;
    int grp = lane >> 2;

    int m0 = blockIdx.y * 128;
    int n0 = blockIdx.x * 128;

    // ldmatrix per-lane source coordinates (within tile)
    int a_row = wm * 64 + (lane & 15);             // + mt*16
    int a_k   = (lane >> 4) * 4;                   // + ks
    int b_row = wn * 32 + (lane & 7) + ((lane >> 4) << 3);  // + pair*16
    int b_k   = ((lane >> 3) & 1) * 4;             // + ks

    // cp.async loader mapping
    int lrow = tid >> 1;
    int cb   = (tid & 1) * 2;
    const float* Ag = A  + (size_t)(m0 + lrow) * K + cb * 4;
    const float* Bg = Bm + (size_t)(n0 + lrow) * K + cb * 4;
    uint32_t As_s = sb + lrow * (GSTR * 4) + cb * 16;
    uint32_t Bs_s = As_s + STAGE_B / 2;

    auto issue_stage = [&](int kt, int s) {
        const float* ag = Ag + kt * 16;
        const float* bg = Bg + kt * 16;
        uint32_t as = As_s + s * STAGE_B;
        uint32_t bs = Bs_s + s * STAGE_B;
        cp16(as, ag);      cp16(as + 16, ag + 4);
        cp16(bs, bg);      cp16(bs + 16, bg + 4);
        cp_commit();
    };

    float acc[4][4][4];
#pragma unroll
    for (int i = 0; i < 4; i++)
#pragma unroll
        for (int j = 0; j < 4; j++)
#pragma unroll
            for (int r = 0; r < 4; r++) acc[i][j][r] = 0.f;

    int niter = K / 16;
    issue_stage(0, 0);
    issue_stage(1, 1);
    issue_stage(2, 2);

    for (int kt = 0; kt < niter; ++kt) {
        int rem = niter - 1 - kt;
        if (rem >= 2)      cp_wait<2>();
        else if (rem == 1) cp_wait<1>();
        else               cp_wait<0>();
        __syncthreads();

        if (kt + 3 < niter) issue_stage(kt + 3, (kt + 3) & 3);

        uint32_t Ab = sb + (uint32_t)(kt & 3) * STAGE_B;
        uint32_t Bb = Ab + STAGE_B / 2;
#pragma unroll
        for (int ks = 0; ks < 16; ks += 8) {
            uint32_t af[4][4];
#pragma unroll
            for (int mt = 0; mt < 4; ++mt)
                ldsm_x4(af[mt],
                        Ab + (((a_row + mt * 16) * GSTR) + ks + a_k) * 4);
            uint32_t bf[2][4];   // [pair]{nt0.b0, nt0.b1, nt1.b0, nt1.b1}
#pragma unroll
            for (int p = 0; p < 2; ++p)
                ldsm_x4(bf[p],
                        Bb + (((b_row + p * 16) * GSTR) + ks + b_k) * 4);
#pragma unroll
            for (int mt = 0; mt < 4; ++mt)
#pragma unroll
                for (int nt = 0; nt < 4; ++nt)
                    mma_tf32(acc[mt][nt], af[mt], &bf[nt >> 1][(nt & 1) * 2]);
        }
    }

#pragma unroll
    for (int mt = 0; mt < 4; ++mt) {
#pragma unroll
        for (int nt = 0; nt < 4; ++nt) {
            int row = m0 + wm * 64 + mt * 16 + grp;
            int col = n0 + wn * 32 + nt * 8 + 2 * tig;
            float v0 = acc[mt][nt][0], v1 = acc[mt][nt][1];
            float v2 = acc[mt][nt][2], v3 = acc[mt][nt][3];
            if (roundC) {
                v0 = to_tf32(v0); v1 = to_tf32(v1);
                v2 = to_tf32(v2); v3 = to_tf32(v3);
            }
            *(float2*)(C + (size_t)row * N + col) = make_float2(v0, v1);
            *(float2*)(C + (size_t)(row + 8) * N + col) = make_float2(v2, v3);
        }
    }
}

// ----------------------------------------------------------------------------
// Tensor-core flash attention, cp.async pipelined, occupancy-2
// (round-12 version, unchanged).
// ----------------------------------------------------------------------------
#define PSTR 68
#define VSTR 72
#define ATTN_SMEM ((128 * PSTR + 64 * PSTR + 64 * VSTR + 128 * PSTR) * 4)

__global__ __launch_bounds__(256, 2) void attn_tc(
    const float* __restrict__ qkv, float* __restrict__ vals)
{
    extern __shared__ float sm[];
    float* Qsm  = sm;                                    // [128][PSTR]
    float* Ksm  = sm + 128 * PSTR;                       // [64][PSTR]
    float* Vsm  = sm + 128 * PSTR + 64 * PSTR;           // [64][VSTR]
    float* Pbuf = sm + 128 * PSTR + 64 * PSTR + 64 * VSTR; // [128][PSTR]

    uint32_t sb = (uint32_t)__cvta_generic_to_shared(sm);
    uint32_t Qs_b = sb;
    uint32_t Ks_b = sb + 128 * PSTR * 4;
    uint32_t Vs_b = Ks_b + 64 * PSTR * 4;

    int tid  = threadIdx.x;
    int lane = tid & 31;
    int warp = tid >> 5;
    int grp  = lane >> 2;
    int tig  = lane & 3;

    int qb = blockIdx.x;
    int h  = blockIdx.y;
    int b  = blockIdx.z;

    const float* base = qkv + (size_t)b * S_ * QKV_N + h * (3 * HD_);
    const float* qg = base;
    const float* kg = base + HD_;
    const float* vg = base + 2 * HD_;
    int q0 = qb * 128;
    int r0 = warp * 16 + grp;

    auto issue_q = [&]() {
#pragma unroll
        for (int p = 0; p < 8; ++p) {
            int idx = tid + p * 256;
            int row = idx >> 4;
            int c   = idx & 15;
            cp16(Qs_b + (row * PSTR + c * 4) * 4,
                 qg + (size_t)(q0 + row) * QKV_N + c * 4);
        }
        cp_commit();
    };
    auto issue_k = [&](int kt) {
#pragma unroll
        for (int p = 0; p < 4; ++p) {
            int idx = tid + p * 256;
            int row = idx >> 4;
            int c   = idx & 15;
            cp16(Ks_b + (row * PSTR + c * 4) * 4,
                 kg + (size_t)(kt + row) * QKV_N + c * 4);
        }
        cp_commit();
    };
    auto issue_v = [&](int kt) {
#pragma unroll
        for (int p = 0; p < 4; ++p) {
            int idx = tid + p * 256;
            int row = idx >> 4;
            int c   = idx & 15;
            cp16(Vs_b + (row * VSTR + c * 4) * 4,
                 vg + (size_t)(kt + row) * QKV_N + c * 4);
        }
        cp_commit();
    };

    issue_q();
    issue_k(0);
    issue_v(0);

    float m_i[2] = {-1e30f, -1e30f};
    float l_i[2] = {0.f, 0.f};
    float oacc[8][4];
#pragma unroll
    for (int nt = 0; nt < 8; ++nt)
#pragma unroll
        for (int r = 0; r < 4; ++r) oacc[nt][r] = 0.f;

    for (int kt = 0; kt < S_; kt += 64) {
        bool last = (kt + 64 >= S_);

        cp_wait<1>();
        __syncthreads();

        float sacc[8][4];
#pragma unroll
        for (int nt = 0; nt < 8; ++nt)
#pragma unroll
            for (int r = 0; r < 4; ++r) sacc[nt][r] = 0.f;

#pragma unroll
        for (int ks = 0; ks < 8; ++ks) {
            uint32_t qf[4];
            qf[0] = __float_as_uint(Qsm[r0 * PSTR + 8 * ks + tig]);
            qf[1] = __float_as_uint(Qsm[(r0 + 8) * PSTR + 8 * ks + tig]);
            qf[2] = __float_as_uint(Qsm[r0 * PSTR + 8 * ks + tig + 4]);
            qf[3] = __float_as_uint(Qsm[(r0 + 8) * PSTR + 8 * ks + tig + 4]);
            uint32_t bf[8][2];
#pragma unroll
            for (int nt = 0; nt < 8; ++nt) {
                bf[nt][0] = __float_as_uint(Ksm[(nt * 8 + grp) * PSTR + 8 * ks + tig]);
                bf[nt][1] = __float_as_uint(Ksm[(nt * 8 + grp) * PSTR + 8 * ks + tig + 4]);
            }
#pragma unroll
            for (int nt = 0; nt < 8; ++nt)
                mma_tf32(sacc[nt], qf, bf[nt]);
        }
        __syncthreads();
        if (!last) issue_k(kt + 64);

        float mx0 = -1e30f, mx1 = -1e30f;
#pragma unroll
        for (int nt = 0; nt < 8; ++nt) {
#pragma unroll
            for (int r = 0; r < 4; ++r) sacc[nt][r] *= 0.125f;
            mx0 = fmaxf(mx0, fmaxf(sacc[nt][0], sacc[nt][1]));
            mx1 = fmaxf(mx1, fmaxf(sacc[nt][2], sacc[nt][3]));
        }
        mx0 = fmaxf(mx0, __shfl_xor_sync(0xffffffffu, mx0, 1));
        mx0 = fmaxf(mx0, __shfl_xor_sync(0xffffffffu, mx0, 2));
        mx1 = fmaxf(mx1, __shfl_xor_sync(0xffffffffu, mx1, 1));
        mx1 = fmaxf(mx1, __shfl_xor_sync(0xffffffffu, mx1, 2));

        float mn0 = fmaxf(m_i[0], mx0);
        float mn1 = fmaxf(m_i[1], mx1);
        float f0 = __expf(m_i[0] - mn0);
        float f1 = __expf(m_i[1] - mn1);
        m_i[0] = mn0; m_i[1] = mn1;

        float rs0 = 0.f, rs1 = 0.f;
#pragma unroll
        for (int nt = 0; nt < 8; ++nt) {
            float p0 = __expf(sacc[nt][0] - mn0);
            float p1 = __expf(sacc[nt][1] - mn0);
            float p2 = __expf(sacc[nt][2] - mn1);
            float p3 = __expf(sacc[nt][3] - mn1);
            rs0 += p0 + p1;
            rs1 += p2 + p3;
            *(float2*)(Pbuf + r0 * PSTR + nt * 8 + 2 * tig) =
                make_float2(to_tf32(p0), to_tf32(p1));
            *(float2*)(Pbuf + (r0 + 8) * PSTR + nt * 8 + 2 * tig) =
                make_float2(to_tf32(p2), to_tf32(p3));
        }
        rs0 += __shfl_xor_sync(0xffffffffu, rs0, 1);
        rs0 += __shfl_xor_sync(0xffffffffu, rs0, 2);
        rs1 += __shfl_xor_sync(0xffffffffu, rs1, 1);
        rs1 += __shfl_xor_sync(0xffffffffu, rs1, 2);
        l_i[0] = l_i[0] * f0 + rs0;
        l_i[1] = l_i[1] * f1 + rs1;

#pragma unroll
        for (int nt = 0; nt < 8; ++nt) {
            oacc[nt][0] *= f0; oacc[nt][1] *= f0;
            oacc[nt][2] *= f1; oacc[nt][3] *= f1;
        }

        if (!last) cp_wait<1>(); else cp_wait<0>();
        __syncthreads();

#pragma unroll
        for (int ks = 0; ks < 8; ++ks) {
            uint32_t af[4];
            af[0] = __float_as_uint(Pbuf[r0 * PSTR + 8 * ks + tig]);
            af[1] = __float_as_uint(Pbuf[(r0 + 8) * PSTR + 8 * ks + tig]);
            af[2] = __float_as_uint(Pbuf[r0 * PSTR + 8 * ks + tig + 4]);
            af[3] = __float_as_uint(Pbuf[(r0 + 8) * PSTR + 8 * ks + tig + 4]);
#pragma unroll
            for (int nt = 0; nt < 8; ++nt) {
                uint32_t bf[2];
                bf[0] = __float_as_uint(Vsm[(8 * ks + tig) * VSTR + nt * 8 + grp]);
                bf[1] = __float_as_uint(Vsm[(8 * ks + tig + 4) * VSTR + nt * 8 + grp]);
                mma_tf32(oacc[nt], af, bf);
            }
        }
        __syncthreads();
        if (!last) issue_v(kt + 64);
    }

    float inv0 = 1.f / l_i[0];
    float inv1 = 1.f / l_i[1];
    size_t row0 = (size_t)b * S_ + q0 + r0;
#pragma unroll
    for (int nt = 0; nt < 8; ++nt) {
        int col = h * HD_ + nt * 8 + 2 * tig;
        *(float2*)(vals + row0 * E_ + col) =
            make_float2(to_tf32(oacc[nt][0] * inv0), to_tf32(oacc[nt][1] * inv0));
        *(float2*)(vals + (row0 + 8) * E_ + col) =
            make_float2(to_tf32(oacc[nt][2] * inv1), to_tf32(oacc[nt][3] * inv1));
    }
}

// ----------------------------------------------------------------------------
// Launch
// ----------------------------------------------------------------------------
extern "C" void kernel_launch(void* const* d_in, const int* in_sizes, int n_in,
                              void* d_out, int out_size)
{
    (void)in_sizes; (void)n_in; (void)out_size;
    const float* x     = (const float*)d_in[0];
    const float* qkv_w = (const float*)d_in[1];
    const float* o_w   = (const float*)d_in[2];
    float* out = (float*)d_out;

    static float *qkv_buf = nullptr, *vals_buf = nullptr;
    static float *xc = nullptr, *wc = nullptr, *oc = nullptr;
    if (qkv_buf == nullptr) {
        cudaGetSymbolAddress((void**)&qkv_buf, g_qkv);
        cudaGetSymbolAddress((void**)&vals_buf, g_vals);
        cudaGetSymbolAddress((void**)&xc, g_xc);
        cudaGetSymbolAddress((void**)&wc, g_wc);
        cudaGetSymbolAddress((void**)&oc, g_oc);
        cudaFuncSetAttribute(attn_tc,
                             cudaFuncAttributeMaxDynamicSharedMemorySize,
                             ATTN_SMEM);
        cudaFuncSetAttribute(gemm_ca,
                             cudaFuncAttributeMaxDynamicSharedMemorySize,
                             GEMM_SMEM);
    }

    dim3 blk(256);
    // 0) Pre-round operands to tf32-valued fp32
    {
        int n4x = M_TOT * D_ / 4;
        int n4w = QKV_N * D_ / 4;
        int n4o = E_ * D_ / 4;
        cvt_tf32_kernel<<<(n4x + 255) / 256, blk>>>(x, xc, n4x);
        cvt_tf32_kernel<<<(n4w + 255) / 256, blk>>>(qkv_w, wc, n4w);
        cvt_tf32_kernel<<<(n4o + 255) / 256, blk>>>(o_w, oc, n4o);
    }
    // 1) qkv = x @ qkv_w^T  (output rounded to tf32 values)
    gemm_ca<<<dim3(QKV_N / 128, M_TOT / 128), blk, GEMM_SMEM>>>(
        xc, wc, qkv_buf, M_TOT, QKV_N, D_, 1);
    // 2) attention -> vals (tf32-rounded)
    attn_tc<<<dim3(S_ / 128, NH_, B_), blk, ATTN_SMEM>>>(qkv_buf, vals_buf);
    // 3) out = vals @ o_w^T  (full fp32 output)
    gemm_ca<<<dim3(E_ / 128, M_TOT / 128), blk, GEMM_SMEM>>>(
        vals_buf, oc, out, M_TOT, E_, D_, 0);
}